// round 9
// baseline (speedup 1.0000x reference)
#include <cuda_runtime.h>
#include <cstdint>

#define N_NODES 100000
#define N_EDGES 1600000
#define E_TOT   1700000   // edges + self-loops

// ---------------- device scratch (no allocations allowed) ----------------
__device__ int   g_is64;
__device__ int   g_deg[N_NODES];
__device__ int   g_rowptr[N_NODES + 1];
__device__ int   g_cursor[N_NODES];
__device__ int   g_src[E_TOT];
__device__ float g_logit[E_TOT];
__device__ __align__(16) float g_h [(size_t)N_NODES * 128];
__device__ __align__(16) float g_h2[(size_t)N_NODES * 128];
__device__ float g_als[N_NODES];
__device__ float g_ald[N_NODES];

#define SBLK 512
#define NBLK ((N_NODES + SBLK - 1) / SBLK)   // 196
__device__ int g_blksum[NBLK];

// Buffer selector: 0 -> g_h, 1 -> g_h2, 2 -> external pointer.
__device__ __forceinline__ float* buf_ptr(int sel, float* ext) {
    if (sel == 0) return g_h;
    if (sel == 1) return g_h2;
    return ext;
}
__device__ __forceinline__ const float* cbuf_ptr(int sel, const float* ext) {
    if (sel == 0) return g_h;
    if (sel == 1) return g_h2;
    return ext;
}

// ---------------- dtype probe + degree zeroing (fused) ----------------
__global__ void detect_zero_kernel(const int* __restrict__ ei32) {
    int i = blockIdx.x * blockDim.x + threadIdx.x;
    if (i < N_NODES) g_deg[i] = 0;
    if (blockIdx.x == 0 && threadIdx.x == 0) {
        int any = 0;
#pragma unroll
        for (int k = 1; k < 128; k += 2) any |= ei32[k];
        g_is64 = (any == 0) ? 1 : 0;
    }
}

__device__ __forceinline__ int edge_at(const void* ei, long long idx) {
    if (g_is64) return (int)((const long long*)ei)[idx];
    return ((const int*)ei)[idx];
}

// ---------------- CSR build ----------------
__global__ void hist_kernel(const void* __restrict__ ei) {
    int e = blockIdx.x * blockDim.x + threadIdx.x;
    if (e >= E_TOT) return;
    int dst = (e < N_EDGES) ? edge_at(ei, (long long)N_EDGES + e) : (e - N_EDGES);
    atomicAdd(&g_deg[dst], 1);
}

__global__ void scan_partial_kernel() {
    __shared__ int s[SBLK];
    int t = threadIdx.x;
    int i = blockIdx.x * SBLK + t;
    s[t] = (i < N_NODES) ? g_deg[i] : 0;
    __syncthreads();
#pragma unroll
    for (int off = SBLK / 2; off > 0; off >>= 1) {
        if (t < off) s[t] += s[t + off];
        __syncthreads();
    }
    if (t == 0) g_blksum[blockIdx.x] = s[0];
}

__global__ void scan_blksum_kernel() {
    __shared__ int s[256];
    int t = threadIdx.x;
    int v = (t < NBLK) ? g_blksum[t] : 0;
    s[t] = v;
    __syncthreads();
#pragma unroll
    for (int off = 1; off < 256; off <<= 1) {
        int u = (t >= off) ? s[t - off] : 0;
        __syncthreads();
        s[t] += u;
        __syncthreads();
    }
    if (t < NBLK) g_blksum[t] = s[t] - v;  // exclusive prefix of block sums
}

__global__ void scan_emit_kernel() {
    __shared__ int s[SBLK];
    int t = threadIdx.x;
    int i = blockIdx.x * SBLK + t;
    int v = (i < N_NODES) ? g_deg[i] : 0;
    s[t] = v;
    __syncthreads();
#pragma unroll
    for (int off = 1; off < SBLK; off <<= 1) {
        int u = (t >= off) ? s[t - off] : 0;
        __syncthreads();
        s[t] += u;
        __syncthreads();
    }
    if (i < N_NODES) {
        int excl = g_blksum[blockIdx.x] + s[t] - v;
        g_rowptr[i] = excl;
        g_cursor[i] = excl;
    }
    if (blockIdx.x == 0 && t == 0) g_rowptr[N_NODES] = E_TOT;
}

__global__ void scatter_kernel(const void* __restrict__ ei) {
    int e = blockIdx.x * blockDim.x + threadIdx.x;
    if (e >= E_TOT) return;
    int src, dst;
    if (e < N_EDGES) {
        src = edge_at(ei, e);
        dst = edge_at(ei, (long long)N_EDGES + e);
    } else {
        src = dst = e - N_EDGES;
    }
    int pos = atomicAdd(&g_cursor[dst], 1);
    g_src[pos] = src;
}

// ---------------- SGEMM: C[M,N] = A[M,K] @ B[K,N] (fp32) ----------------
// Double-buffered smem, float4 global loads, conflict-free As transpose.
// Requires: grid.x == 1 (N == BN), K % BK == 0, BK % 8 == 0, BN/TN == 16.
// DOTS: fused epilogue computing g_als = C.a_s, g_ald = C.a_d per row.
template <int BM, int BN, int BK, int TM, int TN, bool DOTS>
__global__ void sgemm_kernel(int selA, const float* __restrict__ extA,
                             const float* __restrict__ B,
                             int selC, float* __restrict__ extC,
                             const float* __restrict__ a_s,
                             const float* __restrict__ a_d,
                             int M, int N, int K) {
    const float* A = cbuf_ptr(selA, extA);
    float*       C = buf_ptr(selC, extC);

    constexpr int THREADS = (BM / TM) * (BN / TN);
    constexpr int APAIRS  = BM * (BK / 8);
    constexpr int BF4     = BK * BN / 4;
    constexpr int BF4_PT  = (BF4 + THREADS - 1) / THREADS;
    static_assert((BN / TN) == 16, "epilogue assumes 16 lanes per row");
    static_assert(APAIRS <= THREADS, "A loader: at most one pair per thread");

    __shared__ float As[2][BK][BM];
    __shared__ float Bs[2][BK][BN];

    int tid = threadIdx.x;
    int tx = tid % 16;
    int ty = tid / 16;
    int rowBase = blockIdx.y * BM;

    int a_row = tid % BM;
    int a_kh  = tid / BM;
    bool a_on = (tid < APAIRS);
    int a_gm  = rowBase + a_row;

    float4 pa[2];
    float4 pb[BF4_PT];

    auto loadA = [&](int k0) {
        if (a_on && a_gm < M) {
            const float* ap = A + (size_t)a_gm * K + k0 + a_kh * 8;
            pa[0] = *(const float4*)(ap);
            pa[1] = *(const float4*)(ap + 4);
        } else {
            pa[0] = pa[1] = make_float4(0.f, 0.f, 0.f, 0.f);
        }
    };
    auto storeA = [&](int buf) {
        if (a_on) {
            float tmp[8];
            *(float4*)&tmp[0] = pa[0];
            *(float4*)&tmp[4] = pa[1];
#pragma unroll
            for (int j = 0; j < 8; j++) As[buf][a_kh * 8 + j][a_row] = tmp[j];
        }
    };
    auto loadB = [&](int k0) {
#pragma unroll
        for (int b = 0; b < BF4_PT; b++) {
            int idx = tid + b * THREADS;
            if (BF4 % THREADS == 0 || idx < BF4) {
                int kk = idx / (BN / 4);
                int n4 = idx % (BN / 4);
                pb[b] = *(const float4*)(B + (size_t)(k0 + kk) * N + n4 * 4);
            }
        }
    };
    auto storeB = [&](int buf) {
#pragma unroll
        for (int b = 0; b < BF4_PT; b++) {
            int idx = tid + b * THREADS;
            if (BF4 % THREADS == 0 || idx < BF4) {
                int kk = idx / (BN / 4);
                int n4 = idx % (BN / 4);
                *(float4*)&Bs[buf][kk][n4 * 4] = pb[b];
            }
        }
    };

    float acc[TM][TN];
#pragma unroll
    for (int i = 0; i < TM; i++)
#pragma unroll
        for (int j = 0; j < TN; j++) acc[i][j] = 0.f;

    loadA(0); loadB(0);
    storeA(0); storeB(0);
    __syncthreads();

    const int NIT = K / BK;
    for (int it = 0; it < NIT; it++) {
        int cur = it & 1;
        if (it + 1 < NIT) { loadA((it + 1) * BK); loadB((it + 1) * BK); }
#pragma unroll
        for (int kk = 0; kk < BK; kk++) {
            float ra[TM], rb[TN];
#pragma unroll
            for (int i = 0; i < TM; i += 4)
                *(float4*)&ra[i] = *(const float4*)&As[cur][kk][ty * TM + i];
            if constexpr (TN >= 4) {
#pragma unroll
                for (int j = 0; j < TN; j += 4)
                    *(float4*)&rb[j] = *(const float4*)&Bs[cur][kk][tx * TN + j];
            } else {
#pragma unroll
                for (int j = 0; j < TN; j++) rb[j] = Bs[cur][kk][tx * TN + j];
            }
#pragma unroll
            for (int i = 0; i < TM; i++)
#pragma unroll
                for (int j = 0; j < TN; j++) acc[i][j] += ra[i] * rb[j];
        }
        if (it + 1 < NIT) { storeA(cur ^ 1); storeB(cur ^ 1); }
        __syncthreads();
    }

#pragma unroll
    for (int i = 0; i < TM; i++) {
        int gm = rowBase + ty * TM + i;
        if (gm < M) {
            float* cp = C + (size_t)gm * N + tx * TN;
            if constexpr (TN >= 4) {
#pragma unroll
                for (int j = 0; j < TN; j += 4)
                    *(float4*)(cp + j) = *(float4*)&acc[i][j];
            } else {
#pragma unroll
                for (int j = 0; j < TN; j++) cp[j] = acc[i][j];
            }
        }
    }
    if constexpr (DOTS) {
#pragma unroll
        for (int i = 0; i < TM; i++) {
            float ss = 0.f, sd = 0.f;
#pragma unroll
            for (int j = 0; j < TN; j++) {
                int gn = tx * TN + j;
                float c = acc[i][j];
                ss += c * a_s[gn];
                sd += c * a_d[gn];
            }
#pragma unroll
            for (int o = 8; o > 0; o >>= 1) {
                ss += __shfl_xor_sync(0xffffffffu, ss, o);
                sd += __shfl_xor_sync(0xffffffffu, sd, o);
            }
            if (tx == 0) {
                int gm = rowBase + ty * TM + i;
                if (gm < M) { g_als[gm] = ss; g_ald[gm] = sd; }
            }
        }
    }
}

// ---------------- warp-per-dst-node: softmax attention + aggregation ----------------
// Sweep 1: compute logits once, store them, keep running (max, sum) online.
// Sweep 2: weighted feature gather with w = exp(logit - m) / s.
template <int F, bool RELU>
__global__ void attn_agg_kernel(int selH,
                                const float* __restrict__ bias,
                                int selOut, float* __restrict__ extOut) {
    const float* h = cbuf_ptr(selH, nullptr);
    float*     out = buf_ptr(selOut, extOut);
    int t = blockIdx.x * blockDim.x + threadIdx.x;
    int v = t >> 5, lane = t & 31;
    if (v >= N_NODES) return;
    int beg = g_rowptr[v], end = g_rowptr[v + 1];
    float aldv = g_ald[v];

    // sweep 1: logits + online (max, sum)
    float m = -1e30f, s = 0.f;
    for (int p = beg + lane; p < end; p += 32) {
        float l = g_als[g_src[p]] + aldv;
        l = (l > 0.f) ? l : 0.2f * l;   // leaky_relu slope 0.2
        g_logit[p] = l;
        float mn = fmaxf(m, l);
        s = s * expf(m - mn) + expf(l - mn);
        m = mn;
    }
#pragma unroll
    for (int o = 16; o > 0; o >>= 1) {
        float mo = __shfl_xor_sync(0xffffffffu, m, o);
        float so = __shfl_xor_sync(0xffffffffu, s, o);
        float mn = fmaxf(m, mo);
        s = s * expf(m - mn) + so * expf(mo - mn);
        m = mn;
    }
    __syncwarp();  // make sweep-1 logit writes visible warp-wide
    float inv = 1.0f / s;

    // sweep 2: weighted feature accumulation
    if constexpr (F == 128) {
        float4 acc = make_float4(0.f, 0.f, 0.f, 0.f);
        for (int p = beg; p < end; p++) {
            float w = expf(g_logit[p] - m) * inv;
            const float4 hv = *(const float4*)(h + (size_t)g_src[p] * 128 + lane * 4);
            acc.x += w * hv.x; acc.y += w * hv.y; acc.z += w * hv.z; acc.w += w * hv.w;
        }
        const float4 bv = *(const float4*)(bias + lane * 4);
        acc.x += bv.x; acc.y += bv.y; acc.z += bv.z; acc.w += bv.w;
        if (RELU) {
            acc.x = fmaxf(acc.x, 0.f); acc.y = fmaxf(acc.y, 0.f);
            acc.z = fmaxf(acc.z, 0.f); acc.w = fmaxf(acc.w, 0.f);
        }
        *(float4*)(out + (size_t)v * 128 + lane * 4) = acc;
    } else if constexpr (F == 64) {
        float2 acc = make_float2(0.f, 0.f);
        for (int p = beg; p < end; p++) {
            float w = expf(g_logit[p] - m) * inv;
            const float2 hv = *(const float2*)(h + (size_t)g_src[p] * 64 + lane * 2);
            acc.x += w * hv.x; acc.y += w * hv.y;
        }
        const float2 bv = *(const float2*)(bias + lane * 2);
        acc.x += bv.x; acc.y += bv.y;
        if (RELU) { acc.x = fmaxf(acc.x, 0.f); acc.y = fmaxf(acc.y, 0.f); }
        *(float2*)(out + (size_t)v * 64 + lane * 2) = acc;
    } else {  // F == 16
        float acc = 0.f;
        for (int p = beg; p < end; p++) {
            float w = expf(g_logit[p] - m) * inv;
            if (lane < F) acc += w * h[(size_t)g_src[p] * F + lane];
        }
        if (lane < F) {
            acc += bias[lane];
            if (RELU) acc = fmaxf(acc, 0.f);
            out[(size_t)v * F + lane] = acc;
        }
    }
}

// ---------------- launch ----------------
extern "C" void kernel_launch(void* const* d_in, const int* in_sizes, int n_in,
                              void* d_out, int out_size) {
    const float* x   = (const float*)d_in[0];
    const void*  ei  = d_in[1];          // int32 or int64, detected on device
    const float* W1  = (const float*)d_in[2];
    const float* as1 = (const float*)d_in[3];
    const float* ad1 = (const float*)d_in[4];
    const float* b1  = (const float*)d_in[5];
    const float* W2  = (const float*)d_in[6];
    const float* as2 = (const float*)d_in[7];
    const float* ad2 = (const float*)d_in[8];
    const float* b2  = (const float*)d_in[9];
    const float* W3  = (const float*)d_in[10];
    const float* as3 = (const float*)d_in[11];
    const float* ad3 = (const float*)d_in[12];
    const float* b3  = (const float*)d_in[13];
    float* out = (float*)d_out;

    const int TPB = 256;
    const int nodeWarpBlocks = (N_NODES * 32 + TPB - 1) / TPB;

    // --- CSR build (by dst) ---
    detect_zero_kernel<<<(N_NODES + TPB - 1) / TPB, TPB>>>((const int*)ei);
    hist_kernel<<<(E_TOT + TPB - 1) / TPB, TPB>>>(ei);
    scan_partial_kernel<<<NBLK, SBLK>>>();
    scan_blksum_kernel<<<1, 256>>>();
    scan_emit_kernel<<<NBLK, SBLK>>>();
    scatter_kernel<<<(E_TOT + TPB - 1) / TPB, TPB>>>(ei);

    // --- layer 1: 128 -> 128, relu ---   g_h = x @ W1 (+ fused dots)
    sgemm_kernel<128, 128, 16, 8, 8, true>
        <<<dim3(1, (N_NODES + 127) / 128), 256>>>(2, x, W1, 0, nullptr, as1, ad1,
                                                  N_NODES, 128, 128);
    attn_agg_kernel<128, true><<<nodeWarpBlocks, TPB>>>(0, b1, 1, nullptr);

    // --- layer 2: 128 -> 64, relu ---    g_h = g_h2 @ W2 (+ fused dots)
    sgemm_kernel<128, 64, 16, 8, 4, true>
        <<<dim3(1, (N_NODES + 127) / 128), 256>>>(1, nullptr, W2, 0, nullptr, as2, ad2,
                                                  N_NODES, 64, 128);
    attn_agg_kernel<64, true><<<nodeWarpBlocks, TPB>>>(0, b2, 1, nullptr);

    // --- layer 3: 64 -> 16, no relu ---  g_h = g_h2 @ W3 (+ fused dots)
    sgemm_kernel<64, 16, 16, 4, 1, true>
        <<<dim3(1, (N_NODES + 63) / 64), 256>>>(1, nullptr, W3, 0, nullptr, as3, ad3,
                                                N_NODES, 16, 64);
    attn_agg_kernel<16, false><<<nodeWarpBlocks, TPB>>>(0, b3, 2, out);
}

// round 10
// speedup vs baseline: 1.1752x; 1.1752x over previous
#include <cuda_runtime.h>
#include <cstdint>

#define N_NODES 100000
#define N_EDGES 1600000
#define E_TOT   1700000   // edges + self-loops

// ---------------- device scratch (no allocations allowed) ----------------
__device__ int   g_is64;
__device__ int   g_deg[N_NODES];
__device__ int   g_rowptr[N_NODES + 1];
__device__ int   g_cursor[N_NODES];
__device__ int   g_src[E_TOT];
__device__ float g_logit[E_TOT];
__device__ __align__(16) float g_h [(size_t)N_NODES * 128];
__device__ __align__(16) float g_h2[(size_t)N_NODES * 128];
__device__ float g_als[N_NODES];
__device__ float g_ald[N_NODES];

#define SBLK 512
#define NBLK ((N_NODES + SBLK - 1) / SBLK)   // 196
__device__ int g_blksum[NBLK];

// Buffer selector: 0 -> g_h, 1 -> g_h2, 2 -> external pointer.
__device__ __forceinline__ float* buf_ptr(int sel, float* ext) {
    if (sel == 0) return g_h;
    if (sel == 1) return g_h2;
    return ext;
}
__device__ __forceinline__ const float* cbuf_ptr(int sel, const float* ext) {
    if (sel == 0) return g_h;
    if (sel == 1) return g_h2;
    return ext;
}

// ---------------- dtype probe + degree zeroing (fused) ----------------
__global__ void detect_zero_kernel(const int* __restrict__ ei32) {
    int i = blockIdx.x * blockDim.x + threadIdx.x;
    if (i < N_NODES) g_deg[i] = 0;
    if (blockIdx.x == 0 && threadIdx.x == 0) {
        int any = 0;
#pragma unroll
        for (int k = 1; k < 128; k += 2) any |= ei32[k];
        g_is64 = (any == 0) ? 1 : 0;
    }
}

__device__ __forceinline__ int edge_at(const void* ei, long long idx) {
    if (g_is64) return (int)((const long long*)ei)[idx];
    return ((const int*)ei)[idx];
}

// ---------------- CSR build ----------------
__global__ void hist_kernel(const void* __restrict__ ei) {
    int e = blockIdx.x * blockDim.x + threadIdx.x;
    if (e >= E_TOT) return;
    int dst = (e < N_EDGES) ? edge_at(ei, (long long)N_EDGES + e) : (e - N_EDGES);
    atomicAdd(&g_deg[dst], 1);
}

__global__ void scan_partial_kernel() {
    __shared__ int s[SBLK];
    int t = threadIdx.x;
    int i = blockIdx.x * SBLK + t;
    s[t] = (i < N_NODES) ? g_deg[i] : 0;
    __syncthreads();
#pragma unroll
    for (int off = SBLK / 2; off > 0; off >>= 1) {
        if (t < off) s[t] += s[t + off];
        __syncthreads();
    }
    if (t == 0) g_blksum[blockIdx.x] = s[0];
}

__global__ void scan_blksum_kernel() {
    __shared__ int s[256];
    int t = threadIdx.x;
    int v = (t < NBLK) ? g_blksum[t] : 0;
    s[t] = v;
    __syncthreads();
#pragma unroll
    for (int off = 1; off < 256; off <<= 1) {
        int u = (t >= off) ? s[t - off] : 0;
        __syncthreads();
        s[t] += u;
        __syncthreads();
    }
    if (t < NBLK) g_blksum[t] = s[t] - v;  // exclusive prefix of block sums
}

__global__ void scan_emit_kernel() {
    __shared__ int s[SBLK];
    int t = threadIdx.x;
    int i = blockIdx.x * SBLK + t;
    int v = (i < N_NODES) ? g_deg[i] : 0;
    s[t] = v;
    __syncthreads();
#pragma unroll
    for (int off = 1; off < SBLK; off <<= 1) {
        int u = (t >= off) ? s[t - off] : 0;
        __syncthreads();
        s[t] += u;
        __syncthreads();
    }
    if (i < N_NODES) {
        int excl = g_blksum[blockIdx.x] + s[t] - v;
        g_rowptr[i] = excl;
        g_cursor[i] = excl;
    }
    if (blockIdx.x == 0 && t == 0) g_rowptr[N_NODES] = E_TOT;
}

__global__ void scatter_kernel(const void* __restrict__ ei) {
    int e = blockIdx.x * blockDim.x + threadIdx.x;
    if (e >= E_TOT) return;
    int src, dst;
    if (e < N_EDGES) {
        src = edge_at(ei, e);
        dst = edge_at(ei, (long long)N_EDGES + e);
    } else {
        src = dst = e - N_EDGES;
    }
    int pos = atomicAdd(&g_cursor[dst], 1);
    g_src[pos] = src;
}

// ---------------- SGEMM: C[M,N] = A[M,K] @ B[K,N] (fp32) ----------------
// Double-buffered smem, float4 global loads, conflict-free As transpose.
// Inner product uses packed fma.rn.f32x2 (FFMA2) when TN % 4 == 0: Bs float4
// loads are already 2 packed f32x2 operands; only the A value needs a
// broadcast pack. Bitwise-identical fp32 arithmetic, half the FMA issues.
// Requires: grid.x == 1 (N == BN), K % BK == 0, BK % 8 == 0, BN/TN == 16.
// DOTS: fused epilogue computing g_als = C.a_s, g_ald = C.a_d per row.
template <int BM, int BN, int BK, int TM, int TN, bool DOTS>
__global__ void sgemm_kernel(int selA, const float* __restrict__ extA,
                             const float* __restrict__ B,
                             int selC, float* __restrict__ extC,
                             const float* __restrict__ a_s,
                             const float* __restrict__ a_d,
                             int M, int N, int K) {
    const float* A = cbuf_ptr(selA, extA);
    float*       C = buf_ptr(selC, extC);

    constexpr int THREADS = (BM / TM) * (BN / TN);
    constexpr int APAIRS  = BM * (BK / 8);
    constexpr int BF4     = BK * BN / 4;
    constexpr int BF4_PT  = (BF4 + THREADS - 1) / THREADS;
    constexpr bool PACKED = (TN % 4 == 0);
    static_assert((BN / TN) == 16, "epilogue assumes 16 lanes per row");
    static_assert(APAIRS <= THREADS, "A loader: at most one pair per thread");

    __shared__ float As[2][BK][BM];
    __shared__ float Bs[2][BK][BN];

    int tid = threadIdx.x;
    int tx = tid % 16;
    int ty = tid / 16;
    int rowBase = blockIdx.y * BM;

    int a_row = tid % BM;
    int a_kh  = tid / BM;
    bool a_on = (tid < APAIRS);
    int a_gm  = rowBase + a_row;

    float4 pa[2];
    float4 pb[BF4_PT];

    auto loadA = [&](int k0) {
        if (a_on && a_gm < M) {
            const float* ap = A + (size_t)a_gm * K + k0 + a_kh * 8;
            pa[0] = *(const float4*)(ap);
            pa[1] = *(const float4*)(ap + 4);
        } else {
            pa[0] = pa[1] = make_float4(0.f, 0.f, 0.f, 0.f);
        }
    };
    auto storeA = [&](int buf) {
        if (a_on) {
            float tmp[8];
            *(float4*)&tmp[0] = pa[0];
            *(float4*)&tmp[4] = pa[1];
#pragma unroll
            for (int j = 0; j < 8; j++) As[buf][a_kh * 8 + j][a_row] = tmp[j];
        }
    };
    auto loadB = [&](int k0) {
#pragma unroll
        for (int b = 0; b < BF4_PT; b++) {
            int idx = tid + b * THREADS;
            if (BF4 % THREADS == 0 || idx < BF4) {
                int kk = idx / (BN / 4);
                int n4 = idx % (BN / 4);
                pb[b] = *(const float4*)(B + (size_t)(k0 + kk) * N + n4 * 4);
            }
        }
    };
    auto storeB = [&](int buf) {
#pragma unroll
        for (int b = 0; b < BF4_PT; b++) {
            int idx = tid + b * THREADS;
            if (BF4 % THREADS == 0 || idx < BF4) {
                int kk = idx / (BN / 4);
                int n4 = idx % (BN / 4);
                *(float4*)&Bs[buf][kk][n4 * 4] = pb[b];
            }
        }
    };

    // accumulators: packed f32x2 pairs when PACKED, scalar floats otherwise
    unsigned long long acc2[PACKED ? TM : 1][PACKED ? TN / 2 : 1];
    float acc[TM][TN];
    if constexpr (PACKED) {
#pragma unroll
        for (int i = 0; i < TM; i++)
#pragma unroll
            for (int j = 0; j < TN / 2; j++) acc2[i][j] = 0ULL;
    } else {
#pragma unroll
        for (int i = 0; i < TM; i++)
#pragma unroll
            for (int j = 0; j < TN; j++) acc[i][j] = 0.f;
    }

    loadA(0); loadB(0);
    storeA(0); storeB(0);
    __syncthreads();

    const int NIT = K / BK;
    for (int it = 0; it < NIT; it++) {
        int cur = it & 1;
        if (it + 1 < NIT) { loadA((it + 1) * BK); loadB((it + 1) * BK); }
#pragma unroll
        for (int kk = 0; kk < BK; kk++) {
            float ra[TM];
#pragma unroll
            for (int i = 0; i < TM; i += 4)
                *(float4*)&ra[i] = *(const float4*)&As[cur][kk][ty * TM + i];
            if constexpr (PACKED) {
                float4 rbv[TN / 4];
#pragma unroll
                for (int j = 0; j < TN / 4; j++)
                    rbv[j] = *(const float4*)&Bs[cur][kk][tx * TN + j * 4];
                unsigned long long rb2[TN / 2];
#pragma unroll
                for (int j = 0; j < TN / 4; j++) {
                    asm("mov.b64 %0, {%1, %2};" : "=l"(rb2[2 * j])
                        : "r"(__float_as_uint(rbv[j].x)), "r"(__float_as_uint(rbv[j].y)));
                    asm("mov.b64 %0, {%1, %2};" : "=l"(rb2[2 * j + 1])
                        : "r"(__float_as_uint(rbv[j].z)), "r"(__float_as_uint(rbv[j].w)));
                }
#pragma unroll
                for (int i = 0; i < TM; i++) {
                    unsigned long long ra2;
                    asm("mov.b64 %0, {%1, %1};" : "=l"(ra2) : "r"(__float_as_uint(ra[i])));
#pragma unroll
                    for (int j = 0; j < TN / 2; j++)
                        asm("fma.rn.f32x2 %0, %1, %2, %0;"
                            : "+l"(acc2[i][j]) : "l"(ra2), "l"(rb2[j]));
                }
            } else {
                float rb[TN];
#pragma unroll
                for (int j = 0; j < TN; j++) rb[j] = Bs[cur][kk][tx * TN + j];
#pragma unroll
                for (int i = 0; i < TM; i++)
#pragma unroll
                    for (int j = 0; j < TN; j++) acc[i][j] += ra[i] * rb[j];
            }
        }
        if (it + 1 < NIT) { storeA(cur ^ 1); storeB(cur ^ 1); }
        __syncthreads();
    }

    // unpack packed accumulators into scalar acc for the shared epilogue
    if constexpr (PACKED) {
#pragma unroll
        for (int i = 0; i < TM; i++)
#pragma unroll
            for (int j = 0; j < TN / 2; j++) {
                unsigned int lo, hi;
                asm("mov.b64 {%0, %1}, %2;" : "=r"(lo), "=r"(hi) : "l"(acc2[i][j]));
                acc[i][2 * j]     = __uint_as_float(lo);
                acc[i][2 * j + 1] = __uint_as_float(hi);
            }
    }

#pragma unroll
    for (int i = 0; i < TM; i++) {
        int gm = rowBase + ty * TM + i;
        if (gm < M) {
            float* cp = C + (size_t)gm * N + tx * TN;
            if constexpr (TN >= 4) {
#pragma unroll
                for (int j = 0; j < TN; j += 4)
                    *(float4*)(cp + j) = *(float4*)&acc[i][j];
            } else {
#pragma unroll
                for (int j = 0; j < TN; j++) cp[j] = acc[i][j];
            }
        }
    }
    if constexpr (DOTS) {
#pragma unroll
        for (int i = 0; i < TM; i++) {
            float ss = 0.f, sd = 0.f;
#pragma unroll
            for (int j = 0; j < TN; j++) {
                int gn = tx * TN + j;
                float c = acc[i][j];
                ss += c * a_s[gn];
                sd += c * a_d[gn];
            }
#pragma unroll
            for (int o = 8; o > 0; o >>= 1) {
                ss += __shfl_xor_sync(0xffffffffu, ss, o);
                sd += __shfl_xor_sync(0xffffffffu, sd, o);
            }
            if (tx == 0) {
                int gm = rowBase + ty * TM + i;
                if (gm < M) { g_als[gm] = ss; g_ald[gm] = sd; }
            }
        }
    }
}

// ---------------- warp-per-dst-node: softmax attention + aggregation ----------------
// R5 three-sweep form (empirically the local optimum).
template <int F, bool RELU>
__global__ void attn_agg_kernel(int selH,
                                const float* __restrict__ bias,
                                int selOut, float* __restrict__ extOut) {
    const float* h = cbuf_ptr(selH, nullptr);
    float*     out = buf_ptr(selOut, extOut);
    int t = blockIdx.x * blockDim.x + threadIdx.x;
    int v = t >> 5, lane = t & 31;
    if (v >= N_NODES) return;
    int beg = g_rowptr[v], end = g_rowptr[v + 1];
    float aldv = g_ald[v];

    // sweep 1: logits + max
    float m = -1e30f;
    for (int p = beg + lane; p < end; p += 32) {
        float l = g_als[g_src[p]] + aldv;
        l = (l > 0.f) ? l : 0.2f * l;   // leaky_relu slope 0.2
        g_logit[p] = l;
        m = fmaxf(m, l);
    }
#pragma unroll
    for (int o = 16; o > 0; o >>= 1) m = fmaxf(m, __shfl_xor_sync(0xffffffffu, m, o));

    // sweep 2: exp + sum
    float s = 0.f;
    for (int p = beg + lane; p < end; p += 32) {
        float ex = expf(g_logit[p] - m);
        g_logit[p] = ex;
        s += ex;
    }
#pragma unroll
    for (int o = 16; o > 0; o >>= 1) s += __shfl_xor_sync(0xffffffffu, s, o);
    __syncwarp();  // make sweep-2 writes visible warp-wide
    float inv = 1.0f / s;

    // sweep 3: weighted feature accumulation
    if constexpr (F == 128) {
        float4 acc = make_float4(0.f, 0.f, 0.f, 0.f);
        for (int p = beg; p < end; p++) {
            float w = g_logit[p] * inv;
            const float4 hv = *(const float4*)(h + (size_t)g_src[p] * 128 + lane * 4);
            acc.x += w * hv.x; acc.y += w * hv.y; acc.z += w * hv.z; acc.w += w * hv.w;
        }
        const float4 bv = *(const float4*)(bias + lane * 4);
        acc.x += bv.x; acc.y += bv.y; acc.z += bv.z; acc.w += bv.w;
        if (RELU) {
            acc.x = fmaxf(acc.x, 0.f); acc.y = fmaxf(acc.y, 0.f);
            acc.z = fmaxf(acc.z, 0.f); acc.w = fmaxf(acc.w, 0.f);
        }
        *(float4*)(out + (size_t)v * 128 + lane * 4) = acc;
    } else if constexpr (F == 64) {
        float2 acc = make_float2(0.f, 0.f);
        for (int p = beg; p < end; p++) {
            float w = g_logit[p] * inv;
            const float2 hv = *(const float2*)(h + (size_t)g_src[p] * 64 + lane * 2);
            acc.x += w * hv.x; acc.y += w * hv.y;
        }
        const float2 bv = *(const float2*)(bias + lane * 2);
        acc.x += bv.x; acc.y += bv.y;
        if (RELU) { acc.x = fmaxf(acc.x, 0.f); acc.y = fmaxf(acc.y, 0.f); }
        *(float2*)(out + (size_t)v * 64 + lane * 2) = acc;
    } else {  // F == 16
        float acc = 0.f;
        for (int p = beg; p < end; p++) {
            float w = g_logit[p] * inv;
            if (lane < F) acc += w * h[(size_t)g_src[p] * F + lane];
        }
        if (lane < F) {
            acc += bias[lane];
            if (RELU) acc = fmaxf(acc, 0.f);
            out[(size_t)v * F + lane] = acc;
        }
    }
}

// ---------------- launch ----------------
extern "C" void kernel_launch(void* const* d_in, const int* in_sizes, int n_in,
                              void* d_out, int out_size) {
    const float* x   = (const float*)d_in[0];
    const void*  ei  = d_in[1];          // int32 or int64, detected on device
    const float* W1  = (const float*)d_in[2];
    const float* as1 = (const float*)d_in[3];
    const float* ad1 = (const float*)d_in[4];
    const float* b1  = (const float*)d_in[5];
    const float* W2  = (const float*)d_in[6];
    const float* as2 = (const float*)d_in[7];
    const float* ad2 = (const float*)d_in[8];
    const float* b2  = (const float*)d_in[9];
    const float* W3  = (const float*)d_in[10];
    const float* as3 = (const float*)d_in[11];
    const float* ad3 = (const float*)d_in[12];
    const float* b3  = (const float*)d_in[13];
    float* out = (float*)d_out;

    const int TPB = 256;
    const int nodeWarpBlocks = (N_NODES * 32 + TPB - 1) / TPB;

    // --- CSR build (by dst) ---
    detect_zero_kernel<<<(N_NODES + TPB - 1) / TPB, TPB>>>((const int*)ei);
    hist_kernel<<<(E_TOT + TPB - 1) / TPB, TPB>>>(ei);
    scan_partial_kernel<<<NBLK, SBLK>>>();
    scan_blksum_kernel<<<1, 256>>>();
    scan_emit_kernel<<<NBLK, SBLK>>>();
    scatter_kernel<<<(E_TOT + TPB - 1) / TPB, TPB>>>(ei);

    // --- layer 1: 128 -> 128, relu ---   g_h = x @ W1 (+ fused dots)
    sgemm_kernel<128, 128, 16, 8, 8, true>
        <<<dim3(1, (N_NODES + 127) / 128), 256>>>(2, x, W1, 0, nullptr, as1, ad1,
                                                  N_NODES, 128, 128);
    attn_agg_kernel<128, true><<<nodeWarpBlocks, TPB>>>(0, b1, 1, nullptr);

    // --- layer 2: 128 -> 64, relu ---    g_h = g_h2 @ W2 (+ fused dots)
    sgemm_kernel<128, 64, 16, 8, 4, true>
        <<<dim3(1, (N_NODES + 127) / 128), 256>>>(1, nullptr, W2, 0, nullptr, as2, ad2,
                                                  N_NODES, 64, 128);
    attn_agg_kernel<64, true><<<nodeWarpBlocks, TPB>>>(0, b2, 1, nullptr);

    // --- layer 3: 64 -> 16, no relu ---  g_h = g_h2 @ W3 (+ fused dots)
    sgemm_kernel<64, 16, 16, 4, 1, true>
        <<<dim3(1, (N_NODES + 63) / 64), 256>>>(1, nullptr, W3, 0, nullptr, as3, ad3,
                                                N_NODES, 16, 64);
    attn_agg_kernel<16, false><<<nodeWarpBlocks, TPB>>>(0, b3, 2, out);
}